// round 2
// baseline (speedup 1.0000x reference)
#include <cuda_runtime.h>
#include <cstdint>
#include <cstddef>

// Problem dims
#define BATCH 64
#define EDIM 2048
#define HDIM 1024
#define SLEN 512
#define VOCAB 32000

#define SPLIT_T 32   // split-K for t1/t2 gemms
#define SPLIT_G 16   // split-K for g1/g2 gemms
#define SPLIT_O 2    // split-K for logits gemm

// ---------------- scratch (device globals; no allocation allowed) ----------------
__device__ float d_xT [EDIM * BATCH];                  // x^T   [2048][64]
__device__ float d_h0T[HDIM * BATCH];                  // h0^T  [1024][64]
__device__ float d_mT [HDIM * BATCH];                  // m^T   [1024][64]
__device__ float d_hc [BATCH * HDIM];                  // h rows (for scores) [64][1024]
__device__ float d_hcT[2 * HDIM * BATCH];              // [h|ctx]^T [2048][64]
__device__ float d_sc [BATCH * SLEN];                  // scores/attn [64][512]
__device__ float d_P1 [SPLIT_T * BATCH * HDIM];        // partials x@Wmx
__device__ float d_P2 [SPLIT_T * BATCH * HDIM];        // partials h0@Wmh
__device__ float d_P3 [SPLIT_G * BATCH * 4 * HDIM];    // partials x@Wx
__device__ float d_P4 [SPLIT_G * BATCH * 4 * HDIM];    // partials m@Wm
__device__ float d_PO [SPLIT_O * BATCH * VOCAB];       // partials logits

// ---------------- 64-row transpose: A[64][K] -> At[K][64] ----------------
__global__ void transpose64(const float* __restrict__ A, float* __restrict__ At, int K) {
    __shared__ float tile[32][33];
    int kb = blockIdx.x * 32;
    int mb = blockIdx.y * 32;
    int tx = threadIdx.x, ty = threadIdx.y;  // 32 x 8
#pragma unroll
    for (int i = 0; i < 32; i += 8)
        tile[ty + i][tx] = A[(size_t)(mb + ty + i) * K + kb + tx];
    __syncthreads();
#pragma unroll
    for (int i = 0; i < 32; i += 8)
        At[(size_t)(kb + ty + i) * 64 + mb + tx] = tile[tx][ty + i];
}

// ---------------- cp.async helpers ----------------
#define CP_ASYNC16(saddr, gptr) \
    asm volatile("cp.async.cg.shared.global [%0], [%1], 16;" :: "r"(saddr), "l"(gptr))
#define CP_COMMIT() asm volatile("cp.async.commit_group;")

// ---------------- GEMM v2: C[64][N] = At^T @ W (+bias) ----------------
// At: [K][64] (pre-transposed A), W: [K][N] row-major, N % 128 == 0.
// gridDim.x = N/128, gridDim.y = split-K count (K / Sy divisible by 32).
// If Sy > 1: writes partials at C + blockIdx.y*64*N (bias must be null).
// 256 threads, thread tile 4M x 8N, double-buffered cp.async, FFMA2 inner loop.
__global__ __launch_bounds__(256) void gemm64v2(
    const float* __restrict__ At, const float* __restrict__ W, int K,
    const float* __restrict__ bias, float* __restrict__ C, int N)
{
    __shared__ float As[2][32][64];    //  8KB x2
    __shared__ float Bs[2][32][128];   // 16KB x2   (total 48KB static)

    const int tid  = threadIdx.x;
    const int n0   = blockIdx.x * 128;
    const int Sy   = gridDim.y;
    const int Kc   = K / Sy;
    const int kbeg = blockIdx.y * Kc;
    const int nk   = Kc / 32;
    float* Cb = (Sy > 1) ? (C + (size_t)blockIdx.y * 64 * N) : C;

    const unsigned sA = (unsigned)__cvta_generic_to_shared(&As[0][0][0]);
    const unsigned sB = (unsigned)__cvta_generic_to_shared(&Bs[0][0][0]);

    // A tile is fully contiguous in gmem: rows k0..k0+31 of [K][64].
    // B tile: 32 rows x 128 floats, row stride N.
    const int bRow = tid >> 5;          // f>>5 base for p=0
    const int bC4  = (tid & 31) << 2;

    // prologue: issue tile 0
    {
        const float* ag = At + (size_t)kbeg * 64 + tid * 4;
#pragma unroll
        for (int p = 0; p < 2; p++)
            CP_ASYNC16(sA + (tid + p * 256) * 16, ag + p * 1024);
        const float* bg = W + (size_t)kbeg * N + n0;
#pragma unroll
        for (int p = 0; p < 4; p++)
            CP_ASYNC16(sB + ((bRow + p * 8) * 128 + bC4) * 4,
                       bg + (size_t)(bRow + p * 8) * N + bC4);
        CP_COMMIT();
    }

    const int col  = tid & 15;
    const int row4 = (tid >> 4) << 2;

    unsigned long long acc[4][4];
#pragma unroll
    for (int i = 0; i < 4; i++)
#pragma unroll
        for (int j = 0; j < 4; j++) acc[i][j] = 0ULL;

    for (int t = 0; t < nk; t++) {
        int buf = t & 1;
        // issue tile t+1 into the other buffer
        if (t + 1 < nk) {
            int k0 = kbeg + (t + 1) * 32;
            int ob = (t + 1) & 1;
            const float* ag = At + (size_t)k0 * 64 + tid * 4;
#pragma unroll
            for (int p = 0; p < 2; p++)
                CP_ASYNC16(sA + ob * 8192 + (tid + p * 256) * 16, ag + p * 1024);
            const float* bg = W + (size_t)k0 * N + n0;
#pragma unroll
            for (int p = 0; p < 4; p++)
                CP_ASYNC16(sB + ob * 16384 + ((bRow + p * 8) * 128 + bC4) * 4,
                           bg + (size_t)(bRow + p * 8) * N + bC4);
            CP_COMMIT();
            asm volatile("cp.async.wait_group 1;");
        } else {
            asm volatile("cp.async.wait_group 0;");
        }
        __syncthreads();

#pragma unroll 8
        for (int kk = 0; kk < 32; kk++) {
            float4 av = *(const float4*)&As[buf][kk][row4];
            ulonglong2 b0 = *(const ulonglong2*)&Bs[buf][kk][col * 8];
            ulonglong2 b1 = *(const ulonglong2*)&Bs[buf][kk][col * 8 + 4];
            float a[4] = {av.x, av.y, av.z, av.w};
#pragma unroll
            for (int i = 0; i < 4; i++) {
                unsigned long long ap;
                asm("mov.b64 %0, {%1, %1};" : "=l"(ap) : "r"(__float_as_uint(a[i])));
                asm("fma.rn.f32x2 %0, %1, %2, %0;" : "+l"(acc[i][0]) : "l"(ap), "l"(b0.x));
                asm("fma.rn.f32x2 %0, %1, %2, %0;" : "+l"(acc[i][1]) : "l"(ap), "l"(b0.y));
                asm("fma.rn.f32x2 %0, %1, %2, %0;" : "+l"(acc[i][2]) : "l"(ap), "l"(b1.x));
                asm("fma.rn.f32x2 %0, %1, %2, %0;" : "+l"(acc[i][3]) : "l"(ap), "l"(b1.y));
            }
        }
        __syncthreads();
    }

    // epilogue
#pragma unroll
    for (int i = 0; i < 4; i++) {
        int m = row4 + i;
#pragma unroll
        for (int j = 0; j < 4; j++) {
            int n = n0 + col * 8 + j * 2;
            float2 v;
            unsigned int ulo, uhi;
            asm("mov.b64 {%0, %1}, %2;" : "=r"(ulo), "=r"(uhi) : "l"(acc[i][j]));
            v.x = __uint_as_float(ulo);
            v.y = __uint_as_float(uhi);
            if (bias) { v.x += bias[n]; v.y += bias[n + 1]; }
            *(float2*)(Cb + (size_t)m * N + n) = v;
        }
    }
}

// ---------------- m^T = ((x@Wmx + bmx) * (h0@Wmh + bmh))^T ----------------
__global__ void m_kernel(const float* __restrict__ P1, const float* __restrict__ P2,
                         const float* __restrict__ bmx, const float* __restrict__ bmh,
                         float* __restrict__ mT) {
    int idx = blockIdx.x * 256 + threadIdx.x;  // 65536 total
    int j = idx & (HDIM - 1);
    int b = idx >> 10;
    float a = bmx[j], c = bmh[j];
#pragma unroll
    for (int s = 0; s < SPLIT_T; s++) {
        a += P1[(size_t)s * (BATCH * HDIM) + idx];
        c += P2[(size_t)s * (BATCH * HDIM) + idx];
    }
    mT[(size_t)j * 64 + b] = a * c;
}

// ---------------- gates: reduce g partials, LSTM cell -> h into hc + hcT ----------------
__global__ void gates_kernel(const float* __restrict__ P3, const float* __restrict__ P4,
                             const float* __restrict__ bx, const float* __restrict__ bm,
                             const float* __restrict__ c0,
                             float* __restrict__ hc, float* __restrict__ hcT) {
    int idx = blockIdx.x * 256 + threadIdx.x;  // 65536 = 64*1024
    int b = idx >> 10, j = idx & (HDIM - 1);
    float gv[4];
#pragma unroll
    for (int q = 0; q < 4; q++) {
        int colq = j + q * HDIM;
        float g = bx[colq] + bm[colq];
        size_t off = (size_t)b * (4 * HDIM) + colq;
#pragma unroll
        for (int s = 0; s < SPLIT_G; s++)
            g += P3[(size_t)s * (BATCH * 4 * HDIM) + off] + P4[(size_t)s * (BATCH * 4 * HDIM) + off];
        gv[q] = g;
    }
    float f  = 1.f / (1.f + expf(-gv[0]));
    float ii = 1.f / (1.f + expf(-gv[1]));
    float o  = 1.f / (1.f + expf(-gv[2]));
    float ct = tanhf(gv[3]);
    float c  = f * c0[idx] + ii * ct;
    float h  = o * tanhf(c);
    hc[idx] = h;
    hcT[(size_t)j * 64 + b] = h;
}

// ---------------- attention scores: scores[b][s] = dot(h[b], sv[b][s]) ----------------
__global__ void scores_kernel(const float* __restrict__ hc, const float* __restrict__ sv,
                              float* __restrict__ scores) {
    __shared__ float hs[HDIM];
    int b = blockIdx.x;
    int tid = threadIdx.x;                 // 256 threads = 8 warps
    ((float4*)hs)[tid] = ((const float4*)(hc + (size_t)b * HDIM))[tid];
    __syncthreads();
    int warp = tid >> 5, lane = tid & 31;
#pragma unroll
    for (int si = 0; si < 8; si++) {
        int s = blockIdx.y * 64 + warp * 8 + si;
        const float4* sp = (const float4*)(sv + ((size_t)b * SLEN + s) * HDIM);
        float acc = 0.f;
#pragma unroll
        for (int i = 0; i < 8; i++) {
            float4 v  = sp[lane + 32 * i];
            float4 hv = ((const float4*)hs)[lane + 32 * i];
            acc += v.x * hv.x + v.y * hv.y + v.z * hv.z + v.w * hv.w;
        }
#pragma unroll
        for (int off = 16; off; off >>= 1) acc += __shfl_xor_sync(0xffffffffu, acc, off);
        if (lane == 0) scores[(size_t)b * SLEN + s] = acc;
    }
}

// ---------------- softmax over 512, in place ----------------
__global__ void softmax_kernel(float* __restrict__ scores) {
    __shared__ float red[8];
    int b = blockIdx.x;
    float* rowp = scores + (size_t)b * SLEN;
    int tid = threadIdx.x;  // 256
    float v0 = rowp[tid], v1 = rowp[tid + 256];
    float mx = fmaxf(v0, v1);
#pragma unroll
    for (int off = 16; off; off >>= 1) mx = fmaxf(mx, __shfl_xor_sync(0xffffffffu, mx, off));
    if ((tid & 31) == 0) red[tid >> 5] = mx;
    __syncthreads();
    float m = red[0];
#pragma unroll
    for (int i = 1; i < 8; i++) m = fmaxf(m, red[i]);
    float e0 = expf(v0 - m), e1 = expf(v1 - m);
    float sum = e0 + e1;
#pragma unroll
    for (int off = 16; off; off >>= 1) sum += __shfl_xor_sync(0xffffffffu, sum, off);
    __syncthreads();
    if ((tid & 31) == 0) red[tid >> 5] = sum;
    __syncthreads();
    float tot = 0.f;
#pragma unroll
    for (int i = 0; i < 8; i++) tot += red[i];
    float inv = 1.f / tot;
    rowp[tid] = e0 * inv;
    rowp[tid + 256] = e1 * inv;
}

// ---------------- context^T[H+d][b] = sum_s attn[b][s] * sv[b][s][d] ----------------
__global__ void context_kernel(const float* __restrict__ attn, const float* __restrict__ sv,
                               float* __restrict__ hcT) {
    __shared__ float a[SLEN];
    int b = blockIdx.x;
    int tid = threadIdx.x;  // 256
    a[tid] = attn[(size_t)b * SLEN + tid];
    a[tid + 256] = attn[(size_t)b * SLEN + 256 + tid];
    __syncthreads();
    int d = blockIdx.y * 256 + tid;
    const float* svb = sv + (size_t)b * SLEN * HDIM + d;
    float acc0 = 0.f, acc1 = 0.f, acc2 = 0.f, acc3 = 0.f;
    for (int s = 0; s < SLEN; s += 4) {
        acc0 += a[s + 0] * svb[(size_t)(s + 0) * HDIM];
        acc1 += a[s + 1] * svb[(size_t)(s + 1) * HDIM];
        acc2 += a[s + 2] * svb[(size_t)(s + 2) * HDIM];
        acc3 += a[s + 3] * svb[(size_t)(s + 3) * HDIM];
    }
    hcT[(size_t)(HDIM + d) * 64 + b] = (acc0 + acc1) + (acc2 + acc3);
}

// ---------------- logits reduce: out = PO[0] + PO[1] + bias ----------------
__global__ void reduce_logits(const float* __restrict__ PO, const float* __restrict__ bout,
                              float* __restrict__ out) {
    int idx = blockIdx.x * 256 + threadIdx.x;  // 64*32000 = 2,048,000
    int b = idx / VOCAB;
    int n = idx - b * VOCAB;
    float v = bout[n];
#pragma unroll
    for (int s = 0; s < SPLIT_O; s++)
        v += PO[(size_t)s * (BATCH * VOCAB) + idx];
    out[idx] = v;
}

// ---------------- launch ----------------
extern "C" void kernel_launch(void* const* d_in, const int* in_sizes, int n_in,
                              void* d_out, int out_size) {
    const float* x    = (const float*)d_in[0];
    const float* h0   = (const float*)d_in[1];
    const float* c0   = (const float*)d_in[2];
    const float* sv   = (const float*)d_in[3];
    const float* Wmx  = (const float*)d_in[4];
    const float* bmx  = (const float*)d_in[5];
    const float* Wmh  = (const float*)d_in[6];
    const float* bmh  = (const float*)d_in[7];
    const float* Wx   = (const float*)d_in[8];
    const float* bx   = (const float*)d_in[9];
    const float* Wm   = (const float*)d_in[10];
    const float* bm   = (const float*)d_in[11];
    const float* Wout = (const float*)d_in[12];
    const float* bout = (const float*)d_in[13];
    float* out = (float*)d_out;

    float *xT, *h0T, *mT, *hc, *hcT, *sc, *P1, *P2, *P3, *P4, *PO;
    cudaGetSymbolAddress((void**)&xT,  d_xT);
    cudaGetSymbolAddress((void**)&h0T, d_h0T);
    cudaGetSymbolAddress((void**)&mT,  d_mT);
    cudaGetSymbolAddress((void**)&hc,  d_hc);
    cudaGetSymbolAddress((void**)&hcT, d_hcT);
    cudaGetSymbolAddress((void**)&sc,  d_sc);
    cudaGetSymbolAddress((void**)&P1,  d_P1);
    cudaGetSymbolAddress((void**)&P2,  d_P2);
    cudaGetSymbolAddress((void**)&P3,  d_P3);
    cudaGetSymbolAddress((void**)&P4,  d_P4);
    cudaGetSymbolAddress((void**)&PO,  d_PO);

    dim3 tb(32, 8);
    // transposes of activations
    transpose64<<<dim3(EDIM / 32, 2), tb>>>(x, xT, EDIM);
    transpose64<<<dim3(HDIM / 32, 2), tb>>>(h0, h0T, HDIM);

    // t1 = x@Wmx, t2 = h0@Wmh  (split-K partials)
    gemm64v2<<<dim3(HDIM / 128, SPLIT_T), 256>>>(xT,  Wmx, EDIM, nullptr, P1, HDIM);
    gemm64v2<<<dim3(HDIM / 128, SPLIT_T), 256>>>(h0T, Wmh, HDIM, nullptr, P2, HDIM);
    m_kernel<<<(BATCH * HDIM) / 256, 256>>>(P1, P2, bmx, bmh, mT);

    // g = x@Wx + m@Wm (+biases in gates kernel)
    gemm64v2<<<dim3(4 * HDIM / 128, SPLIT_G), 256>>>(xT, Wx, EDIM, nullptr, P3, 4 * HDIM);
    gemm64v2<<<dim3(4 * HDIM / 128, SPLIT_G), 256>>>(mT, Wm, HDIM, nullptr, P4, 4 * HDIM);
    gates_kernel<<<(BATCH * HDIM) / 256, 256>>>(P3, P4, bx, bm, c0, hc, hcT);

    // attention
    scores_kernel<<<dim3(BATCH, 8), 256>>>(hc, sv, sc);
    softmax_kernel<<<BATCH, 256>>>(sc);
    context_kernel<<<dim3(BATCH, HDIM / 256), 256>>>(sc, sv, hcT);

    // logits = [h|context] @ Wout + bout, split-K 2 + reduce
    gemm64v2<<<dim3(VOCAB / 128, SPLIT_O), 256>>>(hcT, Wout, 2 * HDIM, nullptr, PO, VOCAB);
    reduce_logits<<<(BATCH * VOCAB) / 256, 256>>>(PO, bout, out);
}

// round 4
// speedup vs baseline: 1.5719x; 1.5719x over previous
#include <cuda_runtime.h>
#include <cstdint>
#include <cstddef>

// Problem dims
#define BATCH 64
#define EDIM 2048
#define HDIM 1024
#define SLEN 512
#define VOCAB 32000

#define SPLIT_T 8    // split-K for t1/t2 gemms
#define SPLIT_G 4    // split-K for g1/g2 gemms
#define SPLIT_O 2    // split-K for logits gemm

// ---------------- scratch (device globals; no allocation allowed) ----------------
__device__ float d_m  [BATCH * HDIM];                  // m rows [64][1024]
__device__ float d_hc [BATCH * 2 * HDIM];              // [h | ctx] rows [64][2048]
__device__ float d_sc [BATCH * SLEN];                  // scores/attn [64][512]
__device__ float d_P1 [SPLIT_T * BATCH * HDIM];        // partials x@Wmx
__device__ float d_P2 [SPLIT_T * BATCH * HDIM];        // partials h0@Wmh
__device__ float d_P3 [SPLIT_G * BATCH * 4 * HDIM];    // partials x@Wx
__device__ float d_P4 [SPLIT_G * BATCH * 4 * HDIM];    // partials m@Wm
__device__ float d_PO [SPLIT_O * BATCH * VOCAB];       // partials logits

// ---------------- helpers ----------------
__device__ __forceinline__ void cp_async16(unsigned saddr, const void* gptr) {
    asm volatile("cp.async.cg.shared.global [%0], [%1], 16;" :: "r"(saddr), "l"(gptr));
}
#define CP_COMMIT() asm volatile("cp.async.commit_group;")

__device__ __forceinline__ void tf32split(float x, unsigned& hi, unsigned& lo) {
    asm("cvt.rna.tf32.f32 %0, %1;" : "=r"(hi) : "f"(x));
    float l = x - __uint_as_float(hi);
    asm("cvt.rna.tf32.f32 %0, %1;" : "=r"(lo) : "f"(l));
}

#define MMA_TF32(d, a, b) \
    asm volatile("mma.sync.aligned.m16n8k8.row.col.f32.tf32.tf32.f32 " \
        "{%0,%1,%2,%3}, {%4,%5,%6,%7}, {%8,%9}, {%0,%1,%2,%3};" \
        : "+f"(d[0]), "+f"(d[1]), "+f"(d[2]), "+f"(d[3]) \
        : "r"(a[0]), "r"(a[1]), "r"(a[2]), "r"(a[3]), "r"(b[0]), "r"(b[1]))

// Smem geometry (floats)
#define AS_STRIDE 36   // 64 rows x 32 cols padded to 36
#define BS_STRIDE 132  // 32 rows x 128 cols padded to 132
#define AS_BUF (64 * AS_STRIDE)
#define BS_BUF (32 * BS_STRIDE)
#define SMEM_FLOATS (2 * AS_BUF + 2 * BS_BUF)

// ---------------- tf32 3x GEMM: C[64][N] = A @ W (+bias) ----------------
// A [64][K] row-major, W [K][N] row-major, N % 128 == 0, (K/gridDim.y) % 32 == 0.
// gridDim.y = split-K count; if >1 writes partials at C + blockIdx.y*64*N (bias null).
// 256 threads: warp grid 2(M) x 4(N), warp tile 32x32, mma m16n8k8 tf32, 3x split.
__global__ __launch_bounds__(256) void tf32gemm(
    const float* __restrict__ A, const float* __restrict__ W, int K,
    const float* __restrict__ bias, float* __restrict__ C, int N)
{
    extern __shared__ float sm[];
    float* Asm = sm;                 // [2][64][36]
    float* Bsm = sm + 2 * AS_BUF;    // [2][32][132]

    const int tid  = threadIdx.x;
    const int lane = tid & 31;
    const int warp = tid >> 5;
    const int wm   = warp & 1;   // warp row (0..1) -> 32 M rows
    const int wn   = warp >> 1;  // warp col (0..3) -> 32 N cols
    const int qr   = lane >> 2;  // quad row 0..7
    const int qc   = lane & 3;   // quad col 0..3

    const int n0   = blockIdx.x * 128;
    const int Sy   = gridDim.y;
    const int Kc   = K / Sy;
    const int kbeg = blockIdx.y * Kc;
    const int nk   = Kc / 32;
    float* Cb = (Sy > 1) ? (C + (size_t)blockIdx.y * 64 * N) : C;

    const unsigned sA = (unsigned)__cvta_generic_to_shared(Asm);
    const unsigned sB = (unsigned)__cvta_generic_to_shared(Bsm);

    // A-tile copy coords (2 chunks of 16B per thread)
    const int aR  = tid >> 3;           // row 0..31 (+32 for p=1)
    const int aC  = (tid & 7) * 4;      // col float offset
    // B-tile copy coords (4 chunks per thread)
    const int bR  = tid >> 5;           // row 0..7 (+8p)
    const int bC  = (tid & 31) * 4;

    // prologue: tile 0 -> buf 0
    {
        const float* ag = A + (size_t)aR * K + kbeg + aC;
#pragma unroll
        for (int p = 0; p < 2; p++) {
            unsigned dst = sA + (unsigned)(((aR + p * 32) * AS_STRIDE + aC) * 4);
            cp_async16(dst, ag + (size_t)p * 32 * K);
        }
        const float* bg = W + (size_t)kbeg * N + n0 + bC;
#pragma unroll
        for (int p = 0; p < 4; p++) {
            unsigned dst = sB + (unsigned)(((bR + p * 8) * BS_STRIDE + bC) * 4);
            cp_async16(dst, bg + (size_t)(bR + p * 8) * N);
        }
        CP_COMMIT();
    }

    float d[2][4][4];
#pragma unroll
    for (int i = 0; i < 2; i++)
#pragma unroll
        for (int j = 0; j < 4; j++)
#pragma unroll
            for (int q = 0; q < 4; q++) d[i][j][q] = 0.f;

    for (int t = 0; t < nk; t++) {
        const int buf = t & 1;
        if (t + 1 < nk) {
            const int ob = (t + 1) & 1;
            const int k0 = kbeg + (t + 1) * 32;
            const float* ag = A + (size_t)aR * K + k0 + aC;
#pragma unroll
            for (int p = 0; p < 2; p++) {
                unsigned dst = sA + (unsigned)((ob * AS_BUF + (aR + p * 32) * AS_STRIDE + aC) * 4);
                cp_async16(dst, ag + (size_t)p * 32 * K);
            }
            const float* bg = W + (size_t)k0 * N + n0 + bC;
#pragma unroll
            for (int p = 0; p < 4; p++) {
                unsigned dst = sB + (unsigned)((ob * BS_BUF + (bR + p * 8) * BS_STRIDE + bC) * 4);
                cp_async16(dst, bg + (size_t)(bR + p * 8) * N);
            }
            CP_COMMIT();
            asm volatile("cp.async.wait_group 1;");
        } else {
            asm volatile("cp.async.wait_group 0;");
        }
        __syncthreads();

        const float* Ab = Asm + buf * AS_BUF;
        const float* Bb = Bsm + buf * BS_BUF;

#pragma unroll
        for (int kk = 0; kk < 4; kk++) {
            unsigned ahi[2][4], alo[2][4];
#pragma unroll
            for (int mi = 0; mi < 2; mi++) {
                const int r = wm * 32 + mi * 16 + qr;
                const int c = kk * 8 + qc;
                float a0 = Ab[(r)     * AS_STRIDE + c];
                float a1 = Ab[(r + 8) * AS_STRIDE + c];
                float a2 = Ab[(r)     * AS_STRIDE + c + 4];
                float a3 = Ab[(r + 8) * AS_STRIDE + c + 4];
                tf32split(a0, ahi[mi][0], alo[mi][0]);
                tf32split(a1, ahi[mi][1], alo[mi][1]);
                tf32split(a2, ahi[mi][2], alo[mi][2]);
                tf32split(a3, ahi[mi][3], alo[mi][3]);
            }
            unsigned bhi[4][2], blo[4][2];
#pragma unroll
            for (int ni = 0; ni < 4; ni++) {
                const int rr = kk * 8 + qc;
                const int cc = wn * 32 + ni * 8 + qr;
                float b0 = Bb[(rr)     * BS_STRIDE + cc];
                float b1 = Bb[(rr + 4) * BS_STRIDE + cc];
                tf32split(b0, bhi[ni][0], blo[ni][0]);
                tf32split(b1, bhi[ni][1], blo[ni][1]);
            }
#pragma unroll
            for (int mi = 0; mi < 2; mi++)
#pragma unroll
                for (int ni = 0; ni < 4; ni++) {
                    MMA_TF32(d[mi][ni], ahi[mi], bhi[ni]);
                    MMA_TF32(d[mi][ni], alo[mi], bhi[ni]);
                    MMA_TF32(d[mi][ni], ahi[mi], blo[ni]);
                }
        }
        __syncthreads();
    }

    // epilogue
#pragma unroll
    for (int mi = 0; mi < 2; mi++) {
        const int r = wm * 32 + mi * 16 + qr;
#pragma unroll
        for (int ni = 0; ni < 4; ni++) {
            const int c = n0 + wn * 32 + ni * 8 + qc * 2;
            float2 v0 = make_float2(d[mi][ni][0], d[mi][ni][1]);
            float2 v1 = make_float2(d[mi][ni][2], d[mi][ni][3]);
            if (bias) {
                float2 bb = *(const float2*)(bias + c);
                v0.x += bb.x; v0.y += bb.y; v1.x += bb.x; v1.y += bb.y;
            }
            *(float2*)(Cb + (size_t)r * N + c)       = v0;
            *(float2*)(Cb + (size_t)(r + 8) * N + c) = v1;
        }
    }
}

// ---------------- m = (x@Wmx + bmx) * (h0@Wmh + bmh) (rows) ----------------
__global__ void m_kernel(const float* __restrict__ P1, const float* __restrict__ P2,
                         const float* __restrict__ bmx, const float* __restrict__ bmh,
                         float* __restrict__ m) {
    int idx = blockIdx.x * 256 + threadIdx.x;  // 65536 total
    int j = idx & (HDIM - 1);
    float a = bmx[j], c = bmh[j];
#pragma unroll
    for (int s = 0; s < SPLIT_T; s++) {
        a += P1[(size_t)s * (BATCH * HDIM) + idx];
        c += P2[(size_t)s * (BATCH * HDIM) + idx];
    }
    m[idx] = a * c;
}

// ---------------- gates: reduce g partials, LSTM cell -> h into hc[:, :H] ----------------
__global__ void gates_kernel(const float* __restrict__ P3, const float* __restrict__ P4,
                             const float* __restrict__ bx, const float* __restrict__ bm,
                             const float* __restrict__ c0, float* __restrict__ hc) {
    int idx = blockIdx.x * 256 + threadIdx.x;  // 65536 = 64*1024
    int b = idx >> 10, j = idx & (HDIM - 1);
    float gv[4];
#pragma unroll
    for (int q = 0; q < 4; q++) {
        int colq = j + q * HDIM;
        float g = bx[colq] + bm[colq];
        size_t off = (size_t)b * (4 * HDIM) + colq;
#pragma unroll
        for (int s = 0; s < SPLIT_G; s++)
            g += P3[(size_t)s * (BATCH * 4 * HDIM) + off] + P4[(size_t)s * (BATCH * 4 * HDIM) + off];
        gv[q] = g;
    }
    float f  = 1.f / (1.f + expf(-gv[0]));
    float ii = 1.f / (1.f + expf(-gv[1]));
    float o  = 1.f / (1.f + expf(-gv[2]));
    float ct = tanhf(gv[3]);
    float c  = f * c0[idx] + ii * ct;
    hc[(size_t)b * (2 * HDIM) + j] = o * tanhf(c);
}

// ---------------- attention scores: scores[b][s] = dot(h[b], sv[b][s]) ----------------
__global__ void scores_kernel(const float* __restrict__ hc, const float* __restrict__ sv,
                              float* __restrict__ scores) {
    __shared__ float hs[HDIM];
    int b = blockIdx.x;
    int tid = threadIdx.x;                 // 256 threads = 8 warps
    ((float4*)hs)[tid] = ((const float4*)(hc + (size_t)b * (2 * HDIM)))[tid];
    __syncthreads();
    int warp = tid >> 5, lane = tid & 31;
#pragma unroll
    for (int si = 0; si < 8; si++) {
        int s = blockIdx.y * 64 + warp * 8 + si;
        const float4* sp = (const float4*)(sv + ((size_t)b * SLEN + s) * HDIM);
        float acc = 0.f;
#pragma unroll
        for (int i = 0; i < 8; i++) {
            float4 v  = sp[lane + 32 * i];
            float4 hv = ((const float4*)hs)[lane + 32 * i];
            acc += v.x * hv.x + v.y * hv.y + v.z * hv.z + v.w * hv.w;
        }
#pragma unroll
        for (int off = 16; off; off >>= 1) acc += __shfl_xor_sync(0xffffffffu, acc, off);
        if (lane == 0) scores[(size_t)b * SLEN + s] = acc;
    }
}

// ---------------- softmax over 512, in place ----------------
__global__ void softmax_kernel(float* __restrict__ scores) {
    __shared__ float red[8];
    int b = blockIdx.x;
    float* rowp = scores + (size_t)b * SLEN;
    int tid = threadIdx.x;  // 256
    float v0 = rowp[tid], v1 = rowp[tid + 256];
    float mx = fmaxf(v0, v1);
#pragma unroll
    for (int off = 16; off; off >>= 1) mx = fmaxf(mx, __shfl_xor_sync(0xffffffffu, mx, off));
    if ((tid & 31) == 0) red[tid >> 5] = mx;
    __syncthreads();
    float m = red[0];
#pragma unroll
    for (int i = 1; i < 8; i++) m = fmaxf(m, red[i]);
    float e0 = expf(v0 - m), e1 = expf(v1 - m);
    float sum = e0 + e1;
#pragma unroll
    for (int off = 16; off; off >>= 1) sum += __shfl_xor_sync(0xffffffffu, sum, off);
    __syncthreads();
    if ((tid & 31) == 0) red[tid >> 5] = sum;
    __syncthreads();
    float tot = 0.f;
#pragma unroll
    for (int i = 0; i < 8; i++) tot += red[i];
    float inv = 1.f / tot;
    rowp[tid] = e0 * inv;
    rowp[tid + 256] = e1 * inv;
}

// ---------------- context[b][d] -> hc[:, H + d] ----------------
__global__ void context_kernel(const float* __restrict__ attn, const float* __restrict__ sv,
                               float* __restrict__ hc) {
    __shared__ float a[SLEN];
    int b = blockIdx.x;
    int tid = threadIdx.x;  // 256
    a[tid] = attn[(size_t)b * SLEN + tid];
    a[tid + 256] = attn[(size_t)b * SLEN + 256 + tid];
    __syncthreads();
    int d = blockIdx.y * 256 + tid;
    const float* svb = sv + (size_t)b * SLEN * HDIM + d;
    float acc0 = 0.f, acc1 = 0.f, acc2 = 0.f, acc3 = 0.f;
    for (int s = 0; s < SLEN; s += 4) {
        acc0 += a[s + 0] * svb[(size_t)(s + 0) * HDIM];
        acc1 += a[s + 1] * svb[(size_t)(s + 1) * HDIM];
        acc2 += a[s + 2] * svb[(size_t)(s + 2) * HDIM];
        acc3 += a[s + 3] * svb[(size_t)(s + 3) * HDIM];
    }
    hc[(size_t)b * (2 * HDIM) + HDIM + d] = (acc0 + acc1) + (acc2 + acc3);
}

// ---------------- logits reduce: out = sum_s PO[s] + bias ----------------
__global__ void reduce_logits(const float* __restrict__ PO, const float* __restrict__ bout,
                              float* __restrict__ out) {
    int idx = blockIdx.x * 256 + threadIdx.x;  // 2,048,000
    int b = idx / VOCAB;
    int n = idx - b * VOCAB;
    float v = bout[n];
#pragma unroll
    for (int s = 0; s < SPLIT_O; s++)
        v += PO[(size_t)s * (BATCH * VOCAB) + idx];
    out[idx] = v;
}

// ---------------- launch ----------------
extern "C" void kernel_launch(void* const* d_in, const int* in_sizes, int n_in,
                              void* d_out, int out_size) {
    const float* x    = (const float*)d_in[0];
    const float* h0   = (const float*)d_in[1];
    const float* c0   = (const float*)d_in[2];
    const float* sv   = (const float*)d_in[3];
    const float* Wmx  = (const float*)d_in[4];
    const float* bmx  = (const float*)d_in[5];
    const float* Wmh  = (const float*)d_in[6];
    const float* bmh  = (const float*)d_in[7];
    const float* Wx   = (const float*)d_in[8];
    const float* bx   = (const float*)d_in[9];
    const float* Wm   = (const float*)d_in[10];
    const float* bm   = (const float*)d_in[11];
    const float* Wout = (const float*)d_in[12];
    const float* bout = (const float*)d_in[13];
    float* out = (float*)d_out;

    float *m, *hc, *sc, *P1, *P2, *P3, *P4, *PO;
    cudaGetSymbolAddress((void**)&m,  d_m);
    cudaGetSymbolAddress((void**)&hc, d_hc);
    cudaGetSymbolAddress((void**)&sc, d_sc);
    cudaGetSymbolAddress((void**)&P1, d_P1);
    cudaGetSymbolAddress((void**)&P2, d_P2);
    cudaGetSymbolAddress((void**)&P3, d_P3);
    cudaGetSymbolAddress((void**)&P4, d_P4);
    cudaGetSymbolAddress((void**)&PO, d_PO);

    const int smem = SMEM_FLOATS * 4;  // 52224 bytes
    cudaFuncSetAttribute(tf32gemm, cudaFuncAttributeMaxDynamicSharedMemorySize, smem);

    // t1 = x@Wmx, t2 = h0@Wmh  (split-K partials)
    tf32gemm<<<dim3(HDIM / 128, SPLIT_T), 256, smem>>>(x,  Wmx, EDIM, nullptr, P1, HDIM);
    tf32gemm<<<dim3(HDIM / 128, SPLIT_T), 256, smem>>>(h0, Wmh, HDIM, nullptr, P2, HDIM);
    m_kernel<<<(BATCH * HDIM) / 256, 256>>>(P1, P2, bmx, bmh, m);

    // g = x@Wx + m@Wm (+biases in gates kernel)
    tf32gemm<<<dim3(4 * HDIM / 128, SPLIT_G), 256, smem>>>(x, Wx, EDIM, nullptr, P3, 4 * HDIM);
    tf32gemm<<<dim3(4 * HDIM / 128, SPLIT_G), 256, smem>>>(m, Wm, HDIM, nullptr, P4, 4 * HDIM);
    gates_kernel<<<(BATCH * HDIM) / 256, 256>>>(P3, P4, bx, bm, c0, hc);

    // attention
    scores_kernel<<<dim3(BATCH, 8), 256>>>(hc, sv, sc);
    softmax_kernel<<<BATCH, 256>>>(sc);
    context_kernel<<<dim3(BATCH, HDIM / 256), 256>>>(sc, sv, hc);

    // logits = [h|context] @ Wout + bout, split-K + reduce
    tf32gemm<<<dim3(VOCAB / 128, SPLIT_O), 256, smem>>>(hc, Wout, 2 * HDIM, nullptr, PO, VOCAB);
    reduce_logits<<<(BATCH * VOCAB) / 256, 256>>>(PO, bout, out);
}

// round 5
// speedup vs baseline: 2.1924x; 1.3947x over previous
#include <cuda_runtime.h>
#include <cstdint>
#include <cstddef>

// Problem dims
#define BATCH 64
#define EDIM 2048
#define HDIM 1024
#define SLEN 512
#define VOCAB 32000

#define SPLIT_T 16   // split-K for t1/t2 gemms
#define SPLIT_G 8    // split-K for g1/g2 gemms
#define SPLIT_O 2    // split-K for logits gemm

// ---------------- scratch (device globals; no allocation allowed) ----------------
__device__ float d_m  [BATCH * HDIM];                  // m rows [64][1024]
__device__ float d_hc [BATCH * 2 * HDIM];              // [h | ctx] rows [64][2048]
__device__ float d_sc [BATCH * SLEN];                  // scores/attn [64][512]
__device__ float d_P1 [SPLIT_T * BATCH * HDIM];        // partials x@Wmx
__device__ float d_P2 [SPLIT_T * BATCH * HDIM];        // partials h0@Wmh
__device__ float d_P3 [SPLIT_G * BATCH * 4 * HDIM];    // partials x@Wx
__device__ float d_P4 [SPLIT_G * BATCH * 4 * HDIM];    // partials m@Wm
__device__ float d_PO [SPLIT_O * BATCH * VOCAB];       // partials logits

// ---------------- helpers ----------------
// pack two fp32 into bf16x2 hi parts + bf16x2 lo residuals (memory order: lo half = x)
__device__ __forceinline__ void split2(float x, float y, unsigned& hi, unsigned& lo) {
    asm("cvt.rn.bf16x2.f32 %0, %1, %2;" : "=r"(hi) : "f"(y), "f"(x));
    float hx = __uint_as_float(hi << 16);
    float hy = __uint_as_float(hi & 0xffff0000u);
    asm("cvt.rn.bf16x2.f32 %0, %1, %2;" : "=r"(lo) : "f"(y - hy), "f"(x - hx));
}

__device__ __forceinline__ void ldm_x4(unsigned* r, unsigned saddr) {
    asm volatile("ldmatrix.sync.aligned.m8n8.x4.shared.b16 {%0,%1,%2,%3}, [%4];"
                 : "=r"(r[0]), "=r"(r[1]), "=r"(r[2]), "=r"(r[3]) : "r"(saddr));
}
__device__ __forceinline__ void ldm_x4t(unsigned* r, unsigned saddr) {
    asm volatile("ldmatrix.sync.aligned.m8n8.x4.trans.shared.b16 {%0,%1,%2,%3}, [%4];"
                 : "=r"(r[0]), "=r"(r[1]), "=r"(r[2]), "=r"(r[3]) : "r"(saddr));
}

#define MMA_BF16(d, a, b0, b1) \
    asm volatile("mma.sync.aligned.m16n8k16.row.col.f32.bf16.bf16.f32 " \
        "{%0,%1,%2,%3}, {%4,%5,%6,%7}, {%8,%9}, {%0,%1,%2,%3};" \
        : "+f"(d[0]), "+f"(d[1]), "+f"(d[2]), "+f"(d[3]) \
        : "r"(a[0]), "r"(a[1]), "r"(a[2]), "r"(a[3]), "r"(b0), "r"(b1))

// Smem strides in halfs (bytes: A rows 80B -> 5r mod 8 distinct; B rows 272B -> 17k mod 8 distinct)
#define A_ST 40
#define B_ST 136

// ---------------- bf16 3-term GEMM: C[64][N] = A @ W (+bias) ----------------
// A [64][K] row-major fp32, W [K][N] row-major fp32, N % 128 == 0, (K/gridDim.y) % 32 == 0.
// gridDim.y = split-K; if >1 writes partials at C + blockIdx.y*64*N (bias must be null).
// 256 threads: warps 2(M) x 4(N), warp tile 32x32, mma m16n8k16 bf16,
// D += Ahi*Bhi + Alo*Bhi + Ahi*Blo  (conversions hoisted to smem fill).
__global__ __launch_bounds__(256) void bf16gemm(
    const float* __restrict__ A, const float* __restrict__ W, int K,
    const float* __restrict__ bias, float* __restrict__ C, int N)
{
    __shared__ __align__(16) unsigned short Ahi[64 * A_ST];
    __shared__ __align__(16) unsigned short Alo[64 * A_ST];
    __shared__ __align__(16) unsigned short Bhi[32 * B_ST];
    __shared__ __align__(16) unsigned short Blo[32 * B_ST];

    const int tid  = threadIdx.x;
    const int lane = tid & 31;
    const int warp = tid >> 5;
    const int wm   = warp & 1;   // warp M (0..1) -> 32 rows
    const int wn   = warp >> 1;  // warp N (0..3) -> 32 cols
    const int qr   = lane >> 2;
    const int qc   = lane & 3;

    const int n0   = blockIdx.x * 128;
    const int Sy   = gridDim.y;
    const int Kc   = K / Sy;
    const int kbeg = blockIdx.y * Kc;
    const int nk   = Kc / 32;
    float* Cb = (Sy > 1) ? (C + (size_t)blockIdx.y * 64 * N) : C;

    // copy coords
    const int aR = tid >> 2;          // 0..63
    const int aC = (tid & 3) * 8;     // 0,8,16,24 (halfs/floats in k)
    const int bR = tid >> 3;          // 0..31
    const int bC = (tid & 7) * 16;    // 0..112 (n)

    // register staging for next tile
    float4 ar0, ar1, br0, br1, br2, br3;
    {
        const float* ag = A + (size_t)aR * K + kbeg + aC;
        ar0 = *(const float4*)ag;
        ar1 = *(const float4*)(ag + 4);
        const float* bg = W + (size_t)(kbeg + bR) * N + n0 + bC;
        br0 = *(const float4*)bg;
        br1 = *(const float4*)(bg + 4);
        br2 = *(const float4*)(bg + 8);
        br3 = *(const float4*)(bg + 12);
    }

    float d[2][4][4];
#pragma unroll
    for (int i = 0; i < 2; i++)
#pragma unroll
        for (int j = 0; j < 4; j++)
#pragma unroll
            for (int q = 0; q < 4; q++) d[i][j][q] = 0.f;

    const unsigned sAh = (unsigned)__cvta_generic_to_shared(Ahi);
    const unsigned sAl = (unsigned)__cvta_generic_to_shared(Alo);
    const unsigned sBh = (unsigned)__cvta_generic_to_shared(Bhi);
    const unsigned sBl = (unsigned)__cvta_generic_to_shared(Blo);

    for (int t = 0; t < nk; t++) {
        if (t) __syncthreads();  // previous MMA stage done before overwrite
        // convert + store current tile
        {
            uint4 h, l;
            split2(ar0.x, ar0.y, h.x, l.x);
            split2(ar0.z, ar0.w, h.y, l.y);
            split2(ar1.x, ar1.y, h.z, l.z);
            split2(ar1.z, ar1.w, h.w, l.w);
            *(uint4*)&Ahi[aR * A_ST + aC] = h;
            *(uint4*)&Alo[aR * A_ST + aC] = l;

            split2(br0.x, br0.y, h.x, l.x);
            split2(br0.z, br0.w, h.y, l.y);
            split2(br1.x, br1.y, h.z, l.z);
            split2(br1.z, br1.w, h.w, l.w);
            *(uint4*)&Bhi[bR * B_ST + bC] = h;
            *(uint4*)&Blo[bR * B_ST + bC] = l;

            split2(br2.x, br2.y, h.x, l.x);
            split2(br2.z, br2.w, h.y, l.y);
            split2(br3.x, br3.y, h.z, l.z);
            split2(br3.z, br3.w, h.w, l.w);
            *(uint4*)&Bhi[bR * B_ST + bC + 8] = h;
            *(uint4*)&Blo[bR * B_ST + bC + 8] = l;
        }
        // prefetch next tile into regs (latency hides under MMA stage)
        if (t + 1 < nk) {
            const int k0 = kbeg + (t + 1) * 32;
            const float* ag = A + (size_t)aR * K + k0 + aC;
            ar0 = *(const float4*)ag;
            ar1 = *(const float4*)(ag + 4);
            const float* bg = W + (size_t)(k0 + bR) * N + n0 + bC;
            br0 = *(const float4*)bg;
            br1 = *(const float4*)(bg + 4);
            br2 = *(const float4*)(bg + 8);
            br3 = *(const float4*)(bg + 12);
        }
        __syncthreads();

        // MMA stage: 2 k-chunks of 16
#pragma unroll
        for (int kc = 0; kc < 2; kc++) {
            const unsigned aoff =
                (unsigned)(((wm * 32 + (lane & 15)) * A_ST + kc * 16 + (lane >> 4) * 8) * 2);
            unsigned ah[2][4], al[2][4];
            ldm_x4(ah[0], sAh + aoff);
            ldm_x4(ah[1], sAh + aoff + 16 * A_ST * 2);
            ldm_x4(al[0], sAl + aoff);
            ldm_x4(al[1], sAl + aoff + 16 * A_ST * 2);

            const unsigned boff =
                (unsigned)(((kc * 16 + (lane & 15)) * B_ST + wn * 32 + (lane >> 4) * 8) * 2);
            unsigned bh[2][4], bl[2][4];
            ldm_x4t(bh[0], sBh + boff);
            ldm_x4t(bh[1], sBh + boff + 16 * 2);
            ldm_x4t(bl[0], sBl + boff);
            ldm_x4t(bl[1], sBl + boff + 16 * 2);

#pragma unroll
            for (int mi = 0; mi < 2; mi++)
#pragma unroll
                for (int ni = 0; ni < 4; ni++) {
                    const int p = ni >> 1, q = (ni & 1) * 2;
                    MMA_BF16(d[mi][ni], ah[mi], bh[p][q], bh[p][q + 1]);
                    MMA_BF16(d[mi][ni], al[mi], bh[p][q], bh[p][q + 1]);
                    MMA_BF16(d[mi][ni], ah[mi], bl[p][q], bl[p][q + 1]);
                }
        }
    }

    // epilogue
#pragma unroll
    for (int mi = 0; mi < 2; mi++) {
        const int r = wm * 32 + mi * 16 + qr;
#pragma unroll
        for (int ni = 0; ni < 4; ni++) {
            const int c = n0 + wn * 32 + ni * 8 + qc * 2;
            float2 v0 = make_float2(d[mi][ni][0], d[mi][ni][1]);
            float2 v1 = make_float2(d[mi][ni][2], d[mi][ni][3]);
            if (bias) {
                float2 bb = *(const float2*)(bias + c);
                v0.x += bb.x; v0.y += bb.y; v1.x += bb.x; v1.y += bb.y;
            }
            *(float2*)(Cb + (size_t)r * N + c)       = v0;
            *(float2*)(Cb + (size_t)(r + 8) * N + c) = v1;
        }
    }
}

// ---------------- m = (x@Wmx + bmx) * (h0@Wmh + bmh) (rows) ----------------
__global__ void m_kernel(const float* __restrict__ P1, const float* __restrict__ P2,
                         const float* __restrict__ bmx, const float* __restrict__ bmh,
                         float* __restrict__ m) {
    int idx = blockIdx.x * 256 + threadIdx.x;  // 65536 total
    int j = idx & (HDIM - 1);
    float a = bmx[j], c = bmh[j];
#pragma unroll
    for (int s = 0; s < SPLIT_T; s++) {
        a += P1[(size_t)s * (BATCH * HDIM) + idx];
        c += P2[(size_t)s * (BATCH * HDIM) + idx];
    }
    m[idx] = a * c;
}

// ---------------- gates: reduce g partials, LSTM cell -> h into hc[:, :H] ----------------
__global__ void gates_kernel(const float* __restrict__ P3, const float* __restrict__ P4,
                             const float* __restrict__ bx, const float* __restrict__ bm,
                             const float* __restrict__ c0, float* __restrict__ hc) {
    int idx = blockIdx.x * 256 + threadIdx.x;  // 65536 = 64*1024
    int b = idx >> 10, j = idx & (HDIM - 1);
    float gv[4];
#pragma unroll
    for (int q = 0; q < 4; q++) {
        int colq = j + q * HDIM;
        float g = bx[colq] + bm[colq];
        size_t off = (size_t)b * (4 * HDIM) + colq;
#pragma unroll
        for (int s = 0; s < SPLIT_G; s++)
            g += P3[(size_t)s * (BATCH * 4 * HDIM) + off] + P4[(size_t)s * (BATCH * 4 * HDIM) + off];
        gv[q] = g;
    }
    float f  = 1.f / (1.f + expf(-gv[0]));
    float ii = 1.f / (1.f + expf(-gv[1]));
    float o  = 1.f / (1.f + expf(-gv[2]));
    float ct = tanhf(gv[3]);
    float c  = f * c0[idx] + ii * ct;
    hc[(size_t)b * (2 * HDIM) + j] = o * tanhf(c);
}

// ---------------- attention scores: scores[b][s] = dot(h[b], sv[b][s]) ----------------
__global__ void scores_kernel(const float* __restrict__ hc, const float* __restrict__ sv,
                              float* __restrict__ scores) {
    __shared__ float hs[HDIM];
    int b = blockIdx.x;
    int tid = threadIdx.x;                 // 256 threads = 8 warps
    ((float4*)hs)[tid] = ((const float4*)(hc + (size_t)b * (2 * HDIM)))[tid];
    __syncthreads();
    int warp = tid >> 5, lane = tid & 31;
#pragma unroll
    for (int si = 0; si < 8; si++) {
        int s = blockIdx.y * 64 + warp * 8 + si;
        const float4* sp = (const float4*)(sv + ((size_t)b * SLEN + s) * HDIM);
        float acc = 0.f;
#pragma unroll
        for (int i = 0; i < 8; i++) {
            float4 v  = sp[lane + 32 * i];
            float4 hv = ((const float4*)hs)[lane + 32 * i];
            acc += v.x * hv.x + v.y * hv.y + v.z * hv.z + v.w * hv.w;
        }
#pragma unroll
        for (int off = 16; off; off >>= 1) acc += __shfl_xor_sync(0xffffffffu, acc, off);
        if (lane == 0) scores[(size_t)b * SLEN + s] = acc;
    }
}

// ---------------- softmax over 512, in place ----------------
__global__ void softmax_kernel(float* __restrict__ scores) {
    __shared__ float red[8];
    int b = blockIdx.x;
    float* rowp = scores + (size_t)b * SLEN;
    int tid = threadIdx.x;  // 256
    float v0 = rowp[tid], v1 = rowp[tid + 256];
    float mx = fmaxf(v0, v1);
#pragma unroll
    for (int off = 16; off; off >>= 1) mx = fmaxf(mx, __shfl_xor_sync(0xffffffffu, mx, off));
    if ((tid & 31) == 0) red[tid >> 5] = mx;
    __syncthreads();
    float m = red[0];
#pragma unroll
    for (int i = 1; i < 8; i++) m = fmaxf(m, red[i]);
    float e0 = expf(v0 - m), e1 = expf(v1 - m);
    float sum = e0 + e1;
#pragma unroll
    for (int off = 16; off; off >>= 1) sum += __shfl_xor_sync(0xffffffffu, sum, off);
    __syncthreads();
    if ((tid & 31) == 0) red[tid >> 5] = sum;
    __syncthreads();
    float tot = 0.f;
#pragma unroll
    for (int i = 0; i < 8; i++) tot += red[i];
    float inv = 1.f / tot;
    rowp[tid] = e0 * inv;
    rowp[tid + 256] = e1 * inv;
}

// ---------------- context[b][d] -> hc[:, H + d] ----------------
__global__ void context_kernel(const float* __restrict__ attn, const float* __restrict__ sv,
                               float* __restrict__ hc) {
    __shared__ float a[SLEN];
    int b = blockIdx.x;
    int tid = threadIdx.x;  // 256
    a[tid] = attn[(size_t)b * SLEN + tid];
    a[tid + 256] = attn[(size_t)b * SLEN + 256 + tid];
    __syncthreads();
    int d = blockIdx.y * 256 + tid;
    const float* svb = sv + (size_t)b * SLEN * HDIM + d;
    float acc0 = 0.f, acc1 = 0.f, acc2 = 0.f, acc3 = 0.f;
    for (int s = 0; s < SLEN; s += 4) {
        acc0 += a[s + 0] * svb[(size_t)(s + 0) * HDIM];
        acc1 += a[s + 1] * svb[(size_t)(s + 1) * HDIM];
        acc2 += a[s + 2] * svb[(size_t)(s + 2) * HDIM];
        acc3 += a[s + 3] * svb[(size_t)(s + 3) * HDIM];
    }
    hc[(size_t)b * (2 * HDIM) + HDIM + d] = (acc0 + acc1) + (acc2 + acc3);
}

// ---------------- logits reduce: out = sum_s PO[s] + bias ----------------
__global__ void reduce_logits(const float* __restrict__ PO, const float* __restrict__ bout,
                              float* __restrict__ out) {
    int idx = blockIdx.x * 256 + threadIdx.x;  // 2,048,000
    int b = idx / VOCAB;
    int n = idx - b * VOCAB;
    float v = bout[n];
#pragma unroll
    for (int s = 0; s < SPLIT_O; s++)
        v += PO[(size_t)s * (BATCH * VOCAB) + idx];
    out[idx] = v;
}

// ---------------- launch ----------------
extern "C" void kernel_launch(void* const* d_in, const int* in_sizes, int n_in,
                              void* d_out, int out_size) {
    const float* x    = (const float*)d_in[0];
    const float* h0   = (const float*)d_in[1];
    const float* c0   = (const float*)d_in[2];
    const float* sv   = (const float*)d_in[3];
    const float* Wmx  = (const float*)d_in[4];
    const float* bmx  = (const float*)d_in[5];
    const float* Wmh  = (const float*)d_in[6];
    const float* bmh  = (const float*)d_in[7];
    const float* Wx   = (const float*)d_in[8];
    const float* bx   = (const float*)d_in[9];
    const float* Wm   = (const float*)d_in[10];
    const float* bm   = (const float*)d_in[11];
    const float* Wout = (const float*)d_in[12];
    const float* bout = (const float*)d_in[13];
    float* out = (float*)d_out;

    float *m, *hc, *sc, *P1, *P2, *P3, *P4, *PO;
    cudaGetSymbolAddress((void**)&m,  d_m);
    cudaGetSymbolAddress((void**)&hc, d_hc);
    cudaGetSymbolAddress((void**)&sc, d_sc);
    cudaGetSymbolAddress((void**)&P1, d_P1);
    cudaGetSymbolAddress((void**)&P2, d_P2);
    cudaGetSymbolAddress((void**)&P3, d_P3);
    cudaGetSymbolAddress((void**)&P4, d_P4);
    cudaGetSymbolAddress((void**)&PO, d_PO);

    // t1 = x@Wmx, t2 = h0@Wmh  (split-K partials)
    bf16gemm<<<dim3(HDIM / 128, SPLIT_T), 256>>>(x,  Wmx, EDIM, nullptr, P1, HDIM);
    bf16gemm<<<dim3(HDIM / 128, SPLIT_T), 256>>>(h0, Wmh, HDIM, nullptr, P2, HDIM);
    m_kernel<<<(BATCH * HDIM) / 256, 256>>>(P1, P2, bmx, bmh, m);

    // g = x@Wx + m@Wm (+biases in gates kernel)
    bf16gemm<<<dim3(4 * HDIM / 128, SPLIT_G), 256>>>(x, Wx, EDIM, nullptr, P3, 4 * HDIM);
    bf16gemm<<<dim3(4 * HDIM / 128, SPLIT_G), 256>>>(m, Wm, HDIM, nullptr, P4, 4 * HDIM);
    gates_kernel<<<(BATCH * HDIM) / 256, 256>>>(P3, P4, bx, bm, c0, hc);

    // attention
    scores_kernel<<<dim3(BATCH, 8), 256>>>(hc, sv, sc);
    softmax_kernel<<<BATCH, 256>>>(sc);
    context_kernel<<<dim3(BATCH, HDIM / 256), 256>>>(sc, sv, hc);

    // logits = [h|context] @ Wout + bout, split-K + reduce
    bf16gemm<<<dim3(VOCAB / 128, SPLIT_O), 256>>>(hc, Wout, 2 * HDIM, nullptr, PO, VOCAB);
    reduce_logits<<<(BATCH * VOCAB) / 256, 256>>>(PO, bout, out);
}

// round 6
// speedup vs baseline: 2.4303x; 1.1085x over previous
#include <cuda_runtime.h>
#include <cstdint>
#include <cstddef>
#include <math.h>

// Problem dims
#define BATCH 64
#define EDIM 2048
#define HDIM 1024
#define SLEN 512
#define VOCAB 32000

#define SPLIT_T 16   // split-K for t1/t2 gemms
#define SPLIT_G 16   // split-K for g1/g2 gemms
#define SPLIT_O 4    // split-K for logits gemm
#define ATT_SPLIT 4  // split-S for attention

// ---------------- scratch (device globals; no allocation allowed) ----------------
__device__ float d_m   [BATCH * HDIM];                 // m rows [64][1024]
__device__ float d_hc  [BATCH * 2 * HDIM];             // [h | ctx] rows [64][2048]
__device__ float d_P1  [SPLIT_T * BATCH * HDIM];       // partials x@Wmx
__device__ float d_P2  [SPLIT_T * BATCH * HDIM];       // partials h0@Wmh
__device__ float d_P3  [SPLIT_G * BATCH * 4 * HDIM];   // partials x@Wx
__device__ float d_P4  [SPLIT_G * BATCH * 4 * HDIM];   // partials m@Wm
__device__ float d_PO  [SPLIT_O * BATCH * VOCAB];      // partials logits
__device__ float d_pctx[BATCH * ATT_SPLIT * HDIM];     // attention ctx partials
__device__ float d_pms [BATCH * ATT_SPLIT * 2];        // attention (max, sum) partials

// ---------------- helpers ----------------
// pack two fp32 into bf16x2 hi parts + bf16x2 lo residuals (memory order: lo half = x)
__device__ __forceinline__ void split2(float x, float y, unsigned& hi, unsigned& lo) {
    asm("cvt.rn.bf16x2.f32 %0, %1, %2;" : "=r"(hi) : "f"(y), "f"(x));
    float hx = __uint_as_float(hi << 16);
    float hy = __uint_as_float(hi & 0xffff0000u);
    asm("cvt.rn.bf16x2.f32 %0, %1, %2;" : "=r"(lo) : "f"(y - hy), "f"(x - hx));
}

__device__ __forceinline__ void ldm_x4(unsigned* r, unsigned saddr) {
    asm volatile("ldmatrix.sync.aligned.m8n8.x4.shared.b16 {%0,%1,%2,%3}, [%4];"
                 : "=r"(r[0]), "=r"(r[1]), "=r"(r[2]), "=r"(r[3]) : "r"(saddr));
}
__device__ __forceinline__ void ldm_x4t(unsigned* r, unsigned saddr) {
    asm volatile("ldmatrix.sync.aligned.m8n8.x4.trans.shared.b16 {%0,%1,%2,%3}, [%4];"
                 : "=r"(r[0]), "=r"(r[1]), "=r"(r[2]), "=r"(r[3]) : "r"(saddr));
}

#define MMA_BF16(d, a, b0, b1) \
    asm volatile("mma.sync.aligned.m16n8k16.row.col.f32.bf16.bf16.f32 " \
        "{%0,%1,%2,%3}, {%4,%5,%6,%7}, {%8,%9}, {%0,%1,%2,%3};" \
        : "+f"(d[0]), "+f"(d[1]), "+f"(d[2]), "+f"(d[3]) \
        : "r"(a[0]), "r"(a[1]), "r"(a[2]), "r"(a[3]), "r"(b0), "r"(b1))

// Smem strides in halfs
#define A_ST 40
#define B_ST 136

// ---------------- bf16 3-term GEMM: C[64][N] = A @ W (+bias) ----------------
// A [64][K] row-major fp32, W [K][N] row-major fp32, N % 128 == 0, (K/gridDim.y) % 32 == 0.
// gridDim.y = split-K; if >1 writes partials at C + blockIdx.y*64*N (bias must be null).
__global__ __launch_bounds__(256) void bf16gemm(
    const float* __restrict__ A, const float* __restrict__ W, int K,
    const float* __restrict__ bias, float* __restrict__ C, int N)
{
    __shared__ __align__(16) unsigned short Ahi[64 * A_ST];
    __shared__ __align__(16) unsigned short Alo[64 * A_ST];
    __shared__ __align__(16) unsigned short Bhi[32 * B_ST];
    __shared__ __align__(16) unsigned short Blo[32 * B_ST];

    const int tid  = threadIdx.x;
    const int lane = tid & 31;
    const int warp = tid >> 5;
    const int wm   = warp & 1;
    const int wn   = warp >> 1;
    const int qr   = lane >> 2;
    const int qc   = lane & 3;

    const int n0   = blockIdx.x * 128;
    const int Sy   = gridDim.y;
    const int Kc   = K / Sy;
    const int kbeg = blockIdx.y * Kc;
    const int nk   = Kc / 32;
    float* Cb = (Sy > 1) ? (C + (size_t)blockIdx.y * 64 * N) : C;

    const int aR = tid >> 2;
    const int aC = (tid & 3) * 8;
    const int bR = tid >> 3;
    const int bC = (tid & 7) * 16;

    float4 ar0, ar1, br0, br1, br2, br3;
    {
        const float* ag = A + (size_t)aR * K + kbeg + aC;
        ar0 = *(const float4*)ag;
        ar1 = *(const float4*)(ag + 4);
        const float* bg = W + (size_t)(kbeg + bR) * N + n0 + bC;
        br0 = *(const float4*)bg;
        br1 = *(const float4*)(bg + 4);
        br2 = *(const float4*)(bg + 8);
        br3 = *(const float4*)(bg + 12);
    }

    float d[2][4][4];
#pragma unroll
    for (int i = 0; i < 2; i++)
#pragma unroll
        for (int j = 0; j < 4; j++)
#pragma unroll
            for (int q = 0; q < 4; q++) d[i][j][q] = 0.f;

    const unsigned sAh = (unsigned)__cvta_generic_to_shared(Ahi);
    const unsigned sAl = (unsigned)__cvta_generic_to_shared(Alo);
    const unsigned sBh = (unsigned)__cvta_generic_to_shared(Bhi);
    const unsigned sBl = (unsigned)__cvta_generic_to_shared(Blo);

    for (int t = 0; t < nk; t++) {
        if (t) __syncthreads();
        {
            uint4 h, l;
            split2(ar0.x, ar0.y, h.x, l.x);
            split2(ar0.z, ar0.w, h.y, l.y);
            split2(ar1.x, ar1.y, h.z, l.z);
            split2(ar1.z, ar1.w, h.w, l.w);
            *(uint4*)&Ahi[aR * A_ST + aC] = h;
            *(uint4*)&Alo[aR * A_ST + aC] = l;

            split2(br0.x, br0.y, h.x, l.x);
            split2(br0.z, br0.w, h.y, l.y);
            split2(br1.x, br1.y, h.z, l.z);
            split2(br1.z, br1.w, h.w, l.w);
            *(uint4*)&Bhi[bR * B_ST + bC] = h;
            *(uint4*)&Blo[bR * B_ST + bC] = l;

            split2(br2.x, br2.y, h.x, l.x);
            split2(br2.z, br2.w, h.y, l.y);
            split2(br3.x, br3.y, h.z, l.z);
            split2(br3.z, br3.w, h.w, l.w);
            *(uint4*)&Bhi[bR * B_ST + bC + 8] = h;
            *(uint4*)&Blo[bR * B_ST + bC + 8] = l;
        }
        if (t + 1 < nk) {
            const int k0 = kbeg + (t + 1) * 32;
            const float* ag = A + (size_t)aR * K + k0 + aC;
            ar0 = *(const float4*)ag;
            ar1 = *(const float4*)(ag + 4);
            const float* bg = W + (size_t)(k0 + bR) * N + n0 + bC;
            br0 = *(const float4*)bg;
            br1 = *(const float4*)(bg + 4);
            br2 = *(const float4*)(bg + 8);
            br3 = *(const float4*)(bg + 12);
        }
        __syncthreads();

#pragma unroll
        for (int kc = 0; kc < 2; kc++) {
            const unsigned aoff =
                (unsigned)(((wm * 32 + (lane & 15)) * A_ST + kc * 16 + (lane >> 4) * 8) * 2);
            unsigned ah[2][4], al[2][4];
            ldm_x4(ah[0], sAh + aoff);
            ldm_x4(ah[1], sAh + aoff + 16 * A_ST * 2);
            ldm_x4(al[0], sAl + aoff);
            ldm_x4(al[1], sAl + aoff + 16 * A_ST * 2);

            const unsigned boff =
                (unsigned)(((kc * 16 + (lane & 15)) * B_ST + wn * 32 + (lane >> 4) * 8) * 2);
            unsigned bh[2][4], bl[2][4];
            ldm_x4t(bh[0], sBh + boff);
            ldm_x4t(bh[1], sBh + boff + 16 * 2);
            ldm_x4t(bl[0], sBl + boff);
            ldm_x4t(bl[1], sBl + boff + 16 * 2);

#pragma unroll
            for (int mi = 0; mi < 2; mi++)
#pragma unroll
                for (int ni = 0; ni < 4; ni++) {
                    const int p = ni >> 1, q = (ni & 1) * 2;
                    MMA_BF16(d[mi][ni], ah[mi], bh[p][q], bh[p][q + 1]);
                    MMA_BF16(d[mi][ni], al[mi], bh[p][q], bh[p][q + 1]);
                    MMA_BF16(d[mi][ni], ah[mi], bl[p][q], bl[p][q + 1]);
                }
        }
    }

#pragma unroll
    for (int mi = 0; mi < 2; mi++) {
        const int r = wm * 32 + mi * 16 + qr;
#pragma unroll
        for (int ni = 0; ni < 4; ni++) {
            const int c = n0 + wn * 32 + ni * 8 + qc * 2;
            float2 v0 = make_float2(d[mi][ni][0], d[mi][ni][1]);
            float2 v1 = make_float2(d[mi][ni][2], d[mi][ni][3]);
            if (bias) {
                float2 bb = *(const float2*)(bias + c);
                v0.x += bb.x; v0.y += bb.y; v1.x += bb.x; v1.y += bb.y;
            }
            *(float2*)(Cb + (size_t)r * N + c)       = v0;
            *(float2*)(Cb + (size_t)(r + 8) * N + c) = v1;
        }
    }
}

// ---------------- m = (x@Wmx + bmx) * (h0@Wmh + bmh) (rows) ----------------
__global__ void m_kernel(const float* __restrict__ P1, const float* __restrict__ P2,
                         const float* __restrict__ bmx, const float* __restrict__ bmh,
                         float* __restrict__ m) {
    int idx = blockIdx.x * 256 + threadIdx.x;
    int j = idx & (HDIM - 1);
    float a = bmx[j], c = bmh[j];
#pragma unroll
    for (int s = 0; s < SPLIT_T; s++) {
        a += P1[(size_t)s * (BATCH * HDIM) + idx];
        c += P2[(size_t)s * (BATCH * HDIM) + idx];
    }
    m[idx] = a * c;
}

// ---------------- gates: reduce g partials, LSTM cell -> h into hc[:, :H] ----------------
__global__ void gates_kernel(const float* __restrict__ P3, const float* __restrict__ P4,
                             const float* __restrict__ bx, const float* __restrict__ bm,
                             const float* __restrict__ c0, float* __restrict__ hc) {
    int idx = blockIdx.x * 256 + threadIdx.x;
    int b = idx >> 10, j = idx & (HDIM - 1);
    float gv[4];
#pragma unroll
    for (int q = 0; q < 4; q++) {
        int colq = j + q * HDIM;
        float g = bx[colq] + bm[colq];
        size_t off = (size_t)b * (4 * HDIM) + colq;
#pragma unroll
        for (int s = 0; s < SPLIT_G; s++)
            g += P3[(size_t)s * (BATCH * 4 * HDIM) + off] + P4[(size_t)s * (BATCH * 4 * HDIM) + off];
        gv[q] = g;
    }
    float f  = 1.f / (1.f + expf(-gv[0]));
    float ii = 1.f / (1.f + expf(-gv[1]));
    float o  = 1.f / (1.f + expf(-gv[2]));
    float ct = tanhf(gv[3]);
    float c  = f * c0[idx] + ii * ct;
    hc[(size_t)b * (2 * HDIM) + j] = o * tanhf(c);
}

// ---------------- fused attention partial (flash-style online softmax) ----------------
// grid (B, ATT_SPLIT), 256 threads. Single pass over sv chunk.
__global__ __launch_bounds__(256) void attn_partial(
    const float* __restrict__ hc, const float* __restrict__ sv,
    float* __restrict__ pctx, float* __restrict__ pms)
{
    __shared__ float hs[HDIM];
    __shared__ float rows[8][HDIM];
    __shared__ float sscore[8];

    const int b   = blockIdx.x;
    const int sp  = blockIdx.y;
    const int tid = threadIdx.x;
    const int warp = tid >> 5, lane = tid & 31;

    ((float4*)hs)[tid] = ((const float4*)(hc + (size_t)b * 2 * HDIM))[tid];

    float4 ctx = make_float4(0.f, 0.f, 0.f, 0.f);
    float M = -INFINITY, S = 0.f;

    const float* svb = sv + ((size_t)b * SLEN + sp * (SLEN / ATT_SPLIT)) * HDIM;
    const int niter = (SLEN / ATT_SPLIT) / 8;  // 16

    for (int it = 0; it < niter; it++) {
        __syncthreads();  // prev rows fully consumed; hs visible (it=0)
        // each warp loads one sv row into smem and dots it against h
        const float4* src = (const float4*)(svb + (size_t)(it * 8 + warp) * HDIM);
        float acc = 0.f;
#pragma unroll
        for (int i = 0; i < 8; i++) {
            float4 v = src[lane + 32 * i];
            ((float4*)rows[warp])[lane + 32 * i] = v;
            float4 hv = ((const float4*)hs)[lane + 32 * i];
            acc += v.x * hv.x + v.y * hv.y + v.z * hv.z + v.w * hv.w;
        }
#pragma unroll
        for (int off = 16; off; off >>= 1) acc += __shfl_xor_sync(0xffffffffu, acc, off);
        if (lane == 0) sscore[warp] = acc;
        __syncthreads();

        float sc[8];
        float mx = M;
#pragma unroll
        for (int w = 0; w < 8; w++) { sc[w] = sscore[w]; mx = fmaxf(mx, sc[w]); }
        float scale = expf(M - mx);  // M = -inf -> 0
        float e[8], esum = 0.f;
#pragma unroll
        for (int w = 0; w < 8; w++) { e[w] = expf(sc[w] - mx); esum += e[w]; }
        S = S * scale + esum;
        ctx.x *= scale; ctx.y *= scale; ctx.z *= scale; ctx.w *= scale;
#pragma unroll
        for (int w = 0; w < 8; w++) {
            float4 r = ((const float4*)rows[w])[tid];
            ctx.x += e[w] * r.x; ctx.y += e[w] * r.y;
            ctx.z += e[w] * r.z; ctx.w += e[w] * r.w;
        }
        M = mx;
    }

    ((float4*)(pctx + ((size_t)(b * ATT_SPLIT + sp)) * HDIM))[tid] = ctx;
    if (tid == 0) {
        pms[(b * ATT_SPLIT + sp) * 2]     = M;
        pms[(b * ATT_SPLIT + sp) * 2 + 1] = S;
    }
}

// ---------------- attention combine: ctx -> hc[:, H:2H] ----------------
__global__ void attn_combine(const float* __restrict__ pctx, const float* __restrict__ pms,
                             float* __restrict__ hc) {
    const int b = blockIdx.x, tid = threadIdx.x;
    float Mi[ATT_SPLIT], Si[ATT_SPLIT];
    float Mg = -INFINITY;
#pragma unroll
    for (int i = 0; i < ATT_SPLIT; i++) {
        Mi[i] = pms[(b * ATT_SPLIT + i) * 2];
        Si[i] = pms[(b * ATT_SPLIT + i) * 2 + 1];
        Mg = fmaxf(Mg, Mi[i]);
    }
    float wsum = 0.f, wi[ATT_SPLIT];
#pragma unroll
    for (int i = 0; i < ATT_SPLIT; i++) {
        wi[i] = expf(Mi[i] - Mg);
        wsum += wi[i] * Si[i];
    }
    float inv = 1.f / wsum;
    float4 c = make_float4(0.f, 0.f, 0.f, 0.f);
#pragma unroll
    for (int i = 0; i < ATT_SPLIT; i++) {
        float4 p = ((const float4*)(pctx + ((size_t)(b * ATT_SPLIT + i)) * HDIM))[tid];
        c.x += wi[i] * p.x; c.y += wi[i] * p.y;
        c.z += wi[i] * p.z; c.w += wi[i] * p.w;
    }
    c.x *= inv; c.y *= inv; c.z *= inv; c.w *= inv;
    ((float4*)(hc + (size_t)b * 2 * HDIM + HDIM))[tid] = c;
}

// ---------------- logits reduce: out = sum_s PO[s] + bias ----------------
__global__ void reduce_logits(const float* __restrict__ PO, const float* __restrict__ bout,
                              float* __restrict__ out) {
    int idx = blockIdx.x * 256 + threadIdx.x;
    int b = idx / VOCAB;
    int n = idx - b * VOCAB;
    float v = bout[n];
#pragma unroll
    for (int s = 0; s < SPLIT_O; s++)
        v += PO[(size_t)s * (BATCH * VOCAB) + idx];
    out[idx] = v;
}

// ---------------- launch ----------------
extern "C" void kernel_launch(void* const* d_in, const int* in_sizes, int n_in,
                              void* d_out, int out_size) {
    const float* x    = (const float*)d_in[0];
    const float* h0   = (const float*)d_in[1];
    const float* c0   = (const float*)d_in[2];
    const float* sv   = (const float*)d_in[3];
    const float* Wmx  = (const float*)d_in[4];
    const float* bmx  = (const float*)d_in[5];
    const float* Wmh  = (const float*)d_in[6];
    const float* bmh  = (const float*)d_in[7];
    const float* Wx   = (const float*)d_in[8];
    const float* bx   = (const float*)d_in[9];
    const float* Wm   = (const float*)d_in[10];
    const float* bm   = (const float*)d_in[11];
    const float* Wout = (const float*)d_in[12];
    const float* bout = (const float*)d_in[13];
    float* out = (float*)d_out;

    float *m, *hc, *P1, *P2, *P3, *P4, *PO, *pctx, *pms;
    cudaGetSymbolAddress((void**)&m,    d_m);
    cudaGetSymbolAddress((void**)&hc,   d_hc);
    cudaGetSymbolAddress((void**)&P1,   d_P1);
    cudaGetSymbolAddress((void**)&P2,   d_P2);
    cudaGetSymbolAddress((void**)&P3,   d_P3);
    cudaGetSymbolAddress((void**)&P4,   d_P4);
    cudaGetSymbolAddress((void**)&PO,   d_PO);
    cudaGetSymbolAddress((void**)&pctx, d_pctx);
    cudaGetSymbolAddress((void**)&pms,  d_pms);

    // t1 = x@Wmx, t2 = h0@Wmh  (split-K partials)
    bf16gemm<<<dim3(HDIM / 128, SPLIT_T), 256>>>(x,  Wmx, EDIM, nullptr, P1, HDIM);
    bf16gemm<<<dim3(HDIM / 128, SPLIT_T), 256>>>(h0, Wmh, HDIM, nullptr, P2, HDIM);
    m_kernel<<<(BATCH * HDIM) / 256, 256>>>(P1, P2, bmx, bmh, m);

    // g = x@Wx + m@Wm (+biases in gates kernel)
    bf16gemm<<<dim3(4 * HDIM / 128, SPLIT_G), 256>>>(x, Wx, EDIM, nullptr, P3, 4 * HDIM);
    bf16gemm<<<dim3(4 * HDIM / 128, SPLIT_G), 256>>>(m, Wm, HDIM, nullptr, P4, 4 * HDIM);
    gates_kernel<<<(BATCH * HDIM) / 256, 256>>>(P3, P4, bx, bm, c0, hc);

    // fused attention (single pass over sv)
    attn_partial<<<dim3(BATCH, ATT_SPLIT), 256>>>(hc, sv, pctx, pms);
    attn_combine<<<BATCH, 256>>>(pctx, pms, hc);

    // logits = [h|context] @ Wout + bout, split-K + reduce
    bf16gemm<<<dim3(VOCAB / 128, SPLIT_O), 256>>>(hc, Wout, 2 * HDIM, nullptr, PO, VOCAB);
    reduce_logits<<<(BATCH * VOCAB) / 256, 256>>>(PO, bout, out);
}